// round 16
// baseline (speedup 1.0000x reference)
#include <cuda_runtime.h>
#include <cuda_bf16.h>
#include <math.h>
#include <stdint.h>

#define T_STEPS 512
#define BATCH   1024
#define HID     64
#define B_TILE  8
#define NT      512

__device__ float g_buf0[BATCH * T_STEPS * HID];   // layer0 -> layer1
__device__ float g_buf1[BATCH * T_STEPS * HID];   // layer1 -> layer2

// ---- smem layout ----
// xh: 8 batch rows, stride 400 B. Slots (k-index*2 bytes within row):
//   x region A: slots [0,64)   x region B: slots [64,128)   h: slots [128,192)
//   hi plane at byte 0, lo plane at byte 3200.
#define XH_ROW    400
#define XH_LO     3200
#define OFF_GS    6400                    // 8 batches x 260 floats = 8320 B
#define GS_STRIDE 260
#define OFF_HEAD  14720                   // 2048 floats (LAST only)
#define SM_TOTAL  22912

// tanh.approx.f32: 1 MUFU op (sm_75+), abs err ~1e-4
__device__ __forceinline__ float tanh_a(float x) {
    float r;
    asm("tanh.approx.f32 %0, %1;" : "=f"(r) : "f"(x));
    return r;
}
__device__ __forceinline__ float sigf(float x) {
    return fmaf(tanh_a(0.5f * x), 0.5f, 0.5f);   // 1 MUFU + FMA
}
__device__ __forceinline__ uint32_t packbf(float v0, float v1) {
    __nv_bfloat162 h = __floats2bfloat162_rn(v0, v1);
    return *(uint32_t*)&h;
}
// D += A(16x16) * B(16x8), bf16 in, f32 accum (sm_80+, valid on base sm_100)
__device__ __forceinline__ void mma16816(float* d, const uint32_t* a, uint32_t b0, uint32_t b1) {
    asm volatile("mma.sync.aligned.m16n8k16.row.col.f32.bf16.bf16.f32 "
                 "{%0,%1,%2,%3}, {%4,%5,%6,%7}, {%8,%9}, {%0,%1,%2,%3};"
                 : "+f"(d[0]), "+f"(d[1]), "+f"(d[2]), "+f"(d[3])
                 : "r"(a[0]), "r"(a[1]), "r"(a[2]), "r"(a[3]), "r"(b0), "r"(b1));
}

// store one value as bf16 hi/lo pair at (batch b, slot)
__device__ __forceinline__ void store_bpair(char* smem, int b, int slot, float v) {
    __nv_bfloat16 hi = __float2bfloat16(v);
    __nv_bfloat16 lo = __float2bfloat16(v - __bfloat162float(hi));
    *(__nv_bfloat16*)(smem + b * XH_ROW + slot * 2)         = hi;
    *(__nv_bfloat16*)(smem + XH_LO + b * XH_ROW + slot * 2) = lo;
}

// One CTA = 8 batch elements, 512 threads (16 warps).  [R13 + x/h split]
// Step t:
//   phase A: h-part MMAs (slots 128..191) continue the persistent chains
//            (which already hold the x-part from last phase B); stage gates;
//            store x(t+1) into x region (t+1)&1; bar1.
//   phase B: reset chains + x-part MMAs for t+1 (region (t+1)&1) -- issued
//            first, they overlap the MUFU epilogue; epilogue computes c/h,
//            stores h into slots 128+u; bar2.
template <int IN_W, bool LAST>
__global__ void __launch_bounds__(NT, 1)
lstm_mma(const float* __restrict__ x,     // [B][T][IN_W]
         const float* __restrict__ w_ih,  // [256][IN_W] gate-major rows
         const float* __restrict__ w_hh,  // [256][64]
         const float* __restrict__ b_ih,
         const float* __restrict__ b_hh,
         float* __restrict__ y,           // [B][T][64], or out[B][2] if LAST
         const float* __restrict__ fc1_w, const float* __restrict__ fc1_b,
         const float* __restrict__ fc3_w, const float* __restrict__ fc3_b,
         const float* __restrict__ fc2_w, const float* __restrict__ fc2_b)
{
    constexpr int NKC_X = (IN_W + 15) / 16;   // x k-chunks (1 or 4)

    extern __shared__ char smem[];
    float* gsp   = (float*)(smem + OFF_GS);
    float* headp = (float*)(smem + OFF_HEAD);

    const int tid = threadIdx.x;
    const int wid = tid >> 5, lid = tid & 31;
    const int b0  = blockIdx.x * B_TILE;

    // ---- fragment identity ----
    const int fg = lid >> 2;
    const int fc = lid & 3;
    const int m0 = 16 * wid + fg;
    const int m1 = m0 + 8;
    const int c4 = 2 * fc;

    // ---- A fragments -> registers (x chunks + 4 h chunks), hi/lo, once ----
    uint32_t axhi[NKC_X][4], axlo[NKC_X][4];
    uint32_t ahhi[4][4],     ahlo[4][4];
    {
        auto split = [&](float v0, float v1, uint32_t& hi, uint32_t& lo) {
            float h0f = __bfloat162float(__float2bfloat16(v0));
            float h1f = __bfloat162float(__float2bfloat16(v1));
            hi = packbf(v0, v1);
            lo = packbf(v0 - h0f, v1 - h1f);
        };
        auto wx = [&](int m, int k) -> float {   // x weights (0-padded)
            int r = (m & 3) * HID + (m >> 2);
            return (k < IN_W) ? w_ih[r * IN_W + k] : 0.0f;
        };
        auto wh = [&](int m, int k) -> float {   // h weights
            int r = (m & 3) * HID + (m >> 2);
            return w_hh[r * HID + k];
        };
#pragma unroll
        for (int kc = 0; kc < NKC_X; kc++) {
            int k0 = 16 * kc + c4;
            split(wx(m0, k0),     wx(m0, k0 + 1), axhi[kc][0], axlo[kc][0]);
            split(wx(m1, k0),     wx(m1, k0 + 1), axhi[kc][1], axlo[kc][1]);
            split(wx(m0, k0 + 8), wx(m0, k0 + 9), axhi[kc][2], axlo[kc][2]);
            split(wx(m1, k0 + 8), wx(m1, k0 + 9), axhi[kc][3], axlo[kc][3]);
        }
#pragma unroll
        for (int kc = 0; kc < 4; kc++) {
            int k0 = 16 * kc + c4;
            split(wh(m0, k0),     wh(m0, k0 + 1), ahhi[kc][0], ahlo[kc][0]);
            split(wh(m1, k0),     wh(m1, k0 + 1), ahhi[kc][1], ahlo[kc][1]);
            split(wh(m0, k0 + 8), wh(m0, k0 + 9), ahhi[kc][2], ahlo[kc][2]);
            split(wh(m1, k0 + 8), wh(m1, k0 + 9), ahhi[kc][3], ahlo[kc][3]);
        }
    }

    // B-fragment base pointers (uint32 index steps of 8 per k-chunk)
    const uint32_t* hhi = (const uint32_t*)(smem + fg * XH_ROW + 256 + fc * 4);
    const uint32_t* hlo = (const uint32_t*)(smem + XH_LO + fg * XH_ROW + 256 + fc * 4);

    // ---- epilogue identity + bias ----
    const int u_e = tid & 63, b_e = tid >> 6;
    float4 bias;
    bias.x = b_ih[0 * HID + u_e] + b_hh[0 * HID + u_e];
    bias.y = b_ih[1 * HID + u_e] + b_hh[1 * HID + u_e];
    bias.z = b_ih[2 * HID + u_e] + b_hh[2 * HID + u_e];
    bias.w = b_ih[3 * HID + u_e] + b_hh[3 * HID + u_e];
    float c_state = 0.0f;

    // ---- init: zero xh planes, store x(0) into region 0, prologue x-MMAs ----
    for (int i = tid; i < (2 * XH_LO) / 4; i += NT) ((uint32_t*)smem)[i] = 0u;
    __syncthreads();
    if (IN_W == 64) {
        store_bpair(smem, tid >> 6, tid & 63,
                    x[((size_t)(b0 + (tid >> 6)) * T_STEPS + 0) * IN_W + (tid & 63)]);
    } else if (tid < IN_W * B_TILE) {
        int b = tid / IN_W, k = tid - b * IN_W;
        store_bpair(smem, b, k, x[((size_t)(b0 + b) * T_STEPS + 0) * IN_W + k]);
    }
    __syncthreads();

    float dhh[4], dhl[4], dlh[4];
#pragma unroll
    for (int j = 0; j < 4; j++) { dhh[j] = 0.f; dhl[j] = 0.f; dlh[j] = 0.f; }
    {   // prologue: x(0) part (region 0)
        const uint32_t* xhi = (const uint32_t*)(smem + fg * XH_ROW + fc * 4);
        const uint32_t* xlo = (const uint32_t*)(smem + XH_LO + fg * XH_ROW + fc * 4);
#pragma unroll
        for (int kc = 0; kc < NKC_X; kc++) {
            uint32_t bh0 = xhi[8 * kc], bh1 = xhi[8 * kc + 4];
            uint32_t bl0 = xlo[8 * kc], bl1 = xlo[8 * kc + 4];
            mma16816(dhh, axhi[kc], bh0, bh1);
            mma16816(dhl, axhi[kc], bl0, bl1);
            mma16816(dlh, axlo[kc], bh0, bh1);
        }
    }

    for (int t = 0; t < T_STEPS; t++) {
        // prefetch x(t+1)
        float xpre = 0.f; int pb = 0, pk = 0;
        if (t + 1 < T_STEPS) {
            if (IN_W == 64) {
                pb = tid >> 6; pk = tid & 63;
                xpre = x[((size_t)(b0 + pb) * T_STEPS + (t + 1)) * IN_W + pk];
            } else if (tid < IN_W * B_TILE) {
                pb = tid / IN_W; pk = tid - pb * IN_W;
                xpre = x[((size_t)(b0 + pb) * T_STEPS + (t + 1)) * IN_W + pk];
            }
        }

        // ---- phase A: h-part MMAs continue the chains ----
#pragma unroll
        for (int kc = 0; kc < 4; kc++) {
            uint32_t bh0 = hhi[8 * kc], bh1 = hhi[8 * kc + 4];
            uint32_t bl0 = hlo[8 * kc], bl1 = hlo[8 * kc + 4];
            mma16816(dhh, ahhi[kc], bh0, bh1);
            mma16816(dhl, ahhi[kc], bl0, bl1);
            mma16816(dlh, ahlo[kc], bh0, bh1);
        }
        // store x(t+1) into region (t+1)&1 (hidden under MMA drain)
        if (t + 1 < T_STEPS) {
            int slot = ((t + 1) & 1) * 64 + pk;
            if (IN_W == 64)                 store_bpair(smem, pb, slot, xpre);
            else if (tid < IN_W * B_TILE)   store_bpair(smem, pb, slot, xpre);
        }
        // stage gates: gs[batch][row]
        gsp[(c4 + 0) * GS_STRIDE + m0] = dhh[0] + (dhl[0] + dlh[0]);
        gsp[(c4 + 1) * GS_STRIDE + m0] = dhh[1] + (dhl[1] + dlh[1]);
        gsp[(c4 + 0) * GS_STRIDE + m1] = dhh[2] + (dhl[2] + dlh[2]);
        gsp[(c4 + 1) * GS_STRIDE + m1] = dhh[3] + (dhl[3] + dlh[3]);
        __syncthreads();   // bar1: gates staged; x(t+1) region visible

        // ---- phase B: x-part MMAs for t+1 (first, overlap epilogue) ----
#pragma unroll
        for (int j = 0; j < 4; j++) { dhh[j] = 0.f; dhl[j] = 0.f; dlh[j] = 0.f; }
        if (t + 1 < T_STEPS) {
            const char* xb = smem + ((t + 1) & 1) * 128;
            const uint32_t* xhi = (const uint32_t*)(xb + fg * XH_ROW + fc * 4);
            const uint32_t* xlo = (const uint32_t*)(xb + XH_LO + fg * XH_ROW + fc * 4);
#pragma unroll
            for (int kc = 0; kc < NKC_X; kc++) {
                uint32_t bh0 = xhi[8 * kc], bh1 = xhi[8 * kc + 4];
                uint32_t bl0 = xlo[8 * kc], bl1 = xlo[8 * kc + 4];
                mma16816(dhh, axhi[kc], bh0, bh1);
                mma16816(dhl, axhi[kc], bl0, bl1);
                mma16816(dlh, axlo[kc], bh0, bh1);
            }
        }
        // epilogue for (u_e, b_e)
        {
            float4 g = *(const float4*)(gsp + b_e * GS_STRIDE + 4 * u_e);
            float gi = g.x + bias.x, gf = g.y + bias.y;
            float gg = g.z + bias.z, go = g.w + bias.w;
            float iv = sigf(gi), fv = sigf(gf), gv = tanh_a(gg), ov = sigf(go);
            c_state = fv * c_state + iv * gv;
            float h = ov * tanh_a(c_state);

            store_bpair(smem, b_e, 128 + u_e, h);

            if (!LAST) {
                y[((size_t)(b0 + b_e) * T_STEPS + t) * HID + u_e] = h;
            } else if (t == T_STEPS - 1) {
                headp[b_e * HID + u_e] = h;
            }
        }
        __syncthreads();   // bar2: h(t) complete
    }

    // ---- fused MLP head (LAST only) ----
    if (LAST) {
        float* h_s = headp;            // [8][64]
        float* z1  = headp + 512;      // [8][128]
        float* z2  = headp + 1536;     // [8][64]
        __syncthreads();
        for (int v = tid; v < 8 * 128; v += NT) {
            int b = v >> 7, j = v & 127;
            float s = fc1_b[j];
#pragma unroll 8
            for (int k = 0; k < 64; k++) s += h_s[b * 64 + k] * fc1_w[j * 64 + k];
            z1[b * 128 + j] = fmaxf(s, 0.0f);
        }
        __syncthreads();
        for (int v = tid; v < 8 * 64; v += NT) {
            int b = v >> 6, j = v & 63;
            float s = fc3_b[j];
#pragma unroll 8
            for (int k = 0; k < 128; k++) s += z1[b * 128 + k] * fc3_w[j * 128 + k];
            z2[b * 64 + j] = fmaxf(s, 0.0f);
        }
        __syncthreads();
        if (tid < 16) {
            int b = tid >> 1, j = tid & 1;
            float s = fc2_b[j];
#pragma unroll
            for (int k = 0; k < 64; k++) s += z2[b * 64 + k] * fc2_w[j * 64 + k];
            y[(b0 + b) * 2 + j] = s;
        }
    }
}

extern "C" void kernel_launch(void* const* d_in, const int* in_sizes, int n_in,
                              void* d_out, int out_size)
{
    const float* x     = (const float*)d_in[0];
    const float* w_ih0 = (const float*)d_in[1];
    const float* w_hh0 = (const float*)d_in[2];
    const float* b_ih0 = (const float*)d_in[3];
    const float* b_hh0 = (const float*)d_in[4];
    const float* w_ih1 = (const float*)d_in[5];
    const float* w_hh1 = (const float*)d_in[6];
    const float* b_ih1 = (const float*)d_in[7];
    const float* b_hh1 = (const float*)d_in[8];
    const float* w_ih2 = (const float*)d_in[9];
    const float* w_hh2 = (const float*)d_in[10];
    const float* b_ih2 = (const float*)d_in[11];
    const float* b_hh2 = (const float*)d_in[12];
    const float* fc1_w = (const float*)d_in[13];
    const float* fc1_b = (const float*)d_in[14];
    const float* fc3_w = (const float*)d_in[15];
    const float* fc3_b = (const float*)d_in[16];
    const float* fc2_w = (const float*)d_in[17];
    const float* fc2_b = (const float*)d_in[18];
    float* out = (float*)d_out;

    float *buf0 = nullptr, *buf1 = nullptr;
    cudaGetSymbolAddress((void**)&buf0, g_buf0);
    cudaGetSymbolAddress((void**)&buf1, g_buf1);

    const int GRID = BATCH / B_TILE;   // 128

    lstm_mma<6,  false><<<GRID, NT, SM_TOTAL>>>(x,    w_ih0, w_hh0, b_ih0, b_hh0, buf0,
                                                nullptr, nullptr, nullptr, nullptr, nullptr, nullptr);
    lstm_mma<64, false><<<GRID, NT, SM_TOTAL>>>(buf0, w_ih1, w_hh1, b_ih1, b_hh1, buf1,
                                                nullptr, nullptr, nullptr, nullptr, nullptr, nullptr);
    lstm_mma<64, true ><<<GRID, NT, SM_TOTAL>>>(buf1, w_ih2, w_hh2, b_ih2, b_hh2, out,
                                                fc1_w, fc1_b, fc3_w, fc3_b, fc2_w, fc2_b);
}

// round 17
// speedup vs baseline: 1.6948x; 1.6948x over previous
#include <cuda_runtime.h>
#include <cuda_fp16.h>
#include <math.h>
#include <stdint.h>

#define T_STEPS 512
#define BATCH   1024
#define HID     64
#define B_TILE  8
#define NT      512

__device__ float g_buf0[BATCH * T_STEPS * HID];   // layer0 -> layer1
__device__ float g_buf1[BATCH * T_STEPS * HID];   // layer1 -> layer2

// ---- smem byte offsets ----
#define XH_STRIDE 272                     // bytes per batch row (136 fp16)
#define OFF_GS    2176                    // gate staging: 8 batches x 260 floats
#define GS_STRIDE 260
#define OFF_HEAD  10496                   // 2048 floats (LAST only)
#define SM_TOTAL  18688

// tanh.approx.f32: 1 MUFU op, abs err ~1e-4
__device__ __forceinline__ float tanh_a(float x) {
    float r;
    asm("tanh.approx.f32 %0, %1;" : "=f"(r) : "f"(x));
    return r;
}
__device__ __forceinline__ float sigf(float x) {
    return fmaf(tanh_a(0.5f * x), 0.5f, 0.5f);   // 1 MUFU + FMA
}
__device__ __forceinline__ uint32_t packh(float v0, float v1) {
    __half2 h = __floats2half2_rn(v0, v1);
    return *(uint32_t*)&h;
}
// D += A(16x16) * B(16x8), fp16 in, f32 accum (sm_80+, valid on base sm_100)
__device__ __forceinline__ void mma16816(float* d, const uint32_t* a, uint32_t b0, uint32_t b1) {
    asm volatile("mma.sync.aligned.m16n8k16.row.col.f32.f16.f16.f32 "
                 "{%0,%1,%2,%3}, {%4,%5,%6,%7}, {%8,%9}, {%0,%1,%2,%3};"
                 : "+f"(d[0]), "+f"(d[1]), "+f"(d[2]), "+f"(d[3])
                 : "r"(a[0]), "r"(a[1]), "r"(a[2]), "r"(a[3]), "r"(b0), "r"(b1));
}

// store one xh value as a single fp16
__device__ __forceinline__ void store_x(char* smem, int b, int k, float v) {
    *(__half*)(smem + b * XH_STRIDE + k * 2) = __float2half_rn(v);
}

// One CTA = 8 batch elements, 512 threads (16 warps).  [R13 structure, fp16]
// GEMM: gates[256,8] = W[256,K] @ xh[8,K]^T via mma.sync m16n8k16 fp16;
//   W split hi/lo (fp16x2, exact to 2^-22); xh single fp16 (err 2^-11).
//   TWO passes (Whi*X, Wlo*X) -> 2 independent accumulator chains.
//   Warp w owns gate rows 16w..16w+15; A-fragments persistent in registers.
// Staging: gs[batch][row] floats (stride 260), conflict-free STS.32.
// Epilogue: thread = (u = tid&63, b = tid>>6): one LDS.128 -> 4 gates,
//   tanh.approx activations, c/h update, h + x(t+1) back into xh (fp16).
template <int IN_W, bool LAST>
__global__ void __launch_bounds__(NT, 1)
lstm_mma(const float* __restrict__ x,     // [B][T][IN_W]
         const float* __restrict__ w_ih,  // [256][IN_W] gate-major rows
         const float* __restrict__ w_hh,  // [256][64]
         const float* __restrict__ b_ih,
         const float* __restrict__ b_hh,
         float* __restrict__ y,           // [B][T][64], or out[B][2] if LAST
         const float* __restrict__ fc1_w, const float* __restrict__ fc1_b,
         const float* __restrict__ fc3_w, const float* __restrict__ fc3_b,
         const float* __restrict__ fc2_w, const float* __restrict__ fc2_b)
{
    constexpr int K   = IN_W + HID;        // 70 or 128
    constexpr int NKC = (K + 15) / 16;     // k-chunks of 16 (5 or 8)

    extern __shared__ char smem[];
    float* gsp   = (float*)(smem + OFF_GS);
    float* headp = (float*)(smem + OFF_HEAD);

    const int tid = threadIdx.x;
    const int wid = tid >> 5, lid = tid & 31;
    const int b0  = blockIdx.x * B_TILE;

    // ---- fragment identity ----
    const int fg = lid >> 2;
    const int fc = lid & 3;
    const int m0 = 16 * wid + fg;
    const int m1 = m0 + 8;
    const int c4 = 2 * fc;

    // ---- A fragments (weights) -> registers, fp16 hi/lo split, once ----
    uint32_t ahi[NKC][4], alo[NKC][4];
    {
        auto wv = [&](int m, int k) -> float {
            int r = (m & 3) * HID + (m >> 2);
            if (k < IN_W) return w_ih[r * IN_W + k];
            if (k < K)    return w_hh[r * HID + (k - IN_W)];
            return 0.0f;
        };
#pragma unroll
        for (int kc = 0; kc < NKC; kc++) {
            int k0 = 16 * kc + c4;
            float v[8] = { wv(m0, k0),     wv(m0, k0 + 1),
                           wv(m1, k0),     wv(m1, k0 + 1),
                           wv(m0, k0 + 8), wv(m0, k0 + 9),
                           wv(m1, k0 + 8), wv(m1, k0 + 9) };
#pragma unroll
            for (int j = 0; j < 4; j++) {
                float h0f = __half2float(__float2half_rn(v[2 * j]));
                float h1f = __half2float(__float2half_rn(v[2 * j + 1]));
                ahi[kc][j] = packh(v[2 * j], v[2 * j + 1]);
                alo[kc][j] = packh(v[2 * j] - h0f, v[2 * j + 1] - h1f);
            }
        }
    }

    // B-fragment base pointer (single fp16 plane)
    const uint32_t* bp = (const uint32_t*)(smem + fg * XH_STRIDE + c4 * 2);

    // ---- epilogue identity + bias ----
    const int u_e = tid & 63, b_e = tid >> 6;
    float4 bias;
    bias.x = b_ih[0 * HID + u_e] + b_hh[0 * HID + u_e];
    bias.y = b_ih[1 * HID + u_e] + b_hh[1 * HID + u_e];
    bias.z = b_ih[2 * HID + u_e] + b_hh[2 * HID + u_e];
    bias.w = b_ih[3 * HID + u_e] + b_hh[3 * HID + u_e];
    float c_state = 0.0f;

    // ---- init: zero xh plane, then x(0) ----
    for (int i = tid; i < (B_TILE * XH_STRIDE) / 4; i += NT) ((uint32_t*)smem)[i] = 0u;
    __syncthreads();
    if (IN_W == 64) {
        store_x(smem, tid >> 6, tid & 63,
                x[((size_t)(b0 + (tid >> 6)) * T_STEPS + 0) * IN_W + (tid & 63)]);
    } else if (tid < IN_W * B_TILE) {
        int b = tid / IN_W, k = tid - b * IN_W;
        store_x(smem, b, k, x[((size_t)(b0 + b) * T_STEPS + 0) * IN_W + k]);
    }
    __syncthreads();

    for (int t = 0; t < T_STEPS; t++) {
        // prefetch x(t+1)
        float xpre = 0.f; int pb = 0, pk = 0;
        if (t + 1 < T_STEPS) {
            if (IN_W == 64) {
                pb = tid >> 6; pk = tid & 63;
                xpre = x[((size_t)(b0 + pb) * T_STEPS + (t + 1)) * IN_W + pk];
            } else if (tid < IN_W * B_TILE) {
                pb = tid / IN_W; pk = tid - pb * IN_W;
                xpre = x[((size_t)(b0 + pb) * T_STEPS + (t + 1)) * IN_W + pk];
            }
        }

        // ---- GEMM: fp16, 2 independent chains (Whi*X, Wlo*X) ----
        float dh[4] = {0.f, 0.f, 0.f, 0.f};
        float dl[4] = {0.f, 0.f, 0.f, 0.f};
#pragma unroll
        for (int kc = 0; kc < NKC; kc++) {
            uint32_t bF0 = bp[8 * kc], bF1 = bp[8 * kc + 4];
            mma16816(dh, ahi[kc], bF0, bF1);
            mma16816(dl, alo[kc], bF0, bF1);
        }
        // ---- stage: gs[batch][row] (conflict-free STS.32) ----
        gsp[(c4 + 0) * GS_STRIDE + m0] = dh[0] + dl[0];
        gsp[(c4 + 1) * GS_STRIDE + m0] = dh[1] + dl[1];
        gsp[(c4 + 0) * GS_STRIDE + m1] = dh[2] + dl[2];
        gsp[(c4 + 1) * GS_STRIDE + m1] = dh[3] + dl[3];
        __syncthreads();   // gates staged; xh reads for step t done

        // ---- epilogue for (u_e, b_e): rows 4u..4u+3 = (i,f,g,o) ----
        {
            float4 g = *(const float4*)(gsp + b_e * GS_STRIDE + 4 * u_e);
            float gi = g.x + bias.x, gf = g.y + bias.y;
            float gg = g.z + bias.z, go = g.w + bias.w;
            float iv = sigf(gi), fv = sigf(gf), gv = tanh_a(gg), ov = sigf(go);
            c_state = fv * c_state + iv * gv;
            float h = ov * tanh_a(c_state);

            store_x(smem, b_e, IN_W + u_e, h);

            if (!LAST) {
                y[((size_t)(b0 + b_e) * T_STEPS + t) * HID + u_e] = h;
            } else if (t == T_STEPS - 1) {
                headp[b_e * HID + u_e] = h;
            }
        }
        // x(t+1) into xh
        if (t + 1 < T_STEPS) {
            if (IN_W == 64)                 store_x(smem, pb, pk, xpre);
            else if (tid < IN_W * B_TILE)   store_x(smem, pb, pk, xpre);
        }
        __syncthreads();   // xh(t+1) ready
    }

    // ---- fused MLP head (LAST only) ----
    if (LAST) {
        float* h_s = headp;            // [8][64]
        float* z1  = headp + 512;      // [8][128]
        float* z2  = headp + 1536;     // [8][64]
        __syncthreads();
        for (int v = tid; v < 8 * 128; v += NT) {
            int b = v >> 7, j = v & 127;
            float s = fc1_b[j];
#pragma unroll 8
            for (int k = 0; k < 64; k++) s += h_s[b * 64 + k] * fc1_w[j * 64 + k];
            z1[b * 128 + j] = fmaxf(s, 0.0f);
        }
        __syncthreads();
        for (int v = tid; v < 8 * 64; v += NT) {
            int b = v >> 6, j = v & 63;
            float s = fc3_b[j];
#pragma unroll 8
            for (int k = 0; k < 128; k++) s += z1[b * 128 + k] * fc3_w[j * 128 + k];
            z2[b * 64 + j] = fmaxf(s, 0.0f);
        }
        __syncthreads();
        if (tid < 16) {
            int b = tid >> 1, j = tid & 1;
            float s = fc2_b[j];
#pragma unroll
            for (int k = 0; k < 64; k++) s += z2[b * 64 + k] * fc2_w[j * 64 + k];
            y[(b0 + b) * 2 + j] = s;
        }
    }
}

extern "C" void kernel_launch(void* const* d_in, const int* in_sizes, int n_in,
                              void* d_out, int out_size)
{
    const float* x     = (const float*)d_in[0];
    const float* w_ih0 = (const float*)d_in[1];
    const float* w_hh0 = (const float*)d_in[2];
    const float* b_ih0 = (const float*)d_in[3];
    const float* b_hh0 = (const float*)d_in[4];
    const float* w_ih1 = (const float*)d_in[5];
    const float* w_hh1 = (const float*)d_in[6];
    const float* b_ih1 = (const float*)d_in[7];
    const float* b_hh1 = (const float*)d_in[8];
    const float* w_ih2 = (const float*)d_in[9];
    const float* w_hh2 = (const float*)d_in[10];
    const float* b_ih2 = (const float*)d_in[11];
    const float* b_hh2 = (const float*)d_in[12];
    const float* fc1_w = (const float*)d_in[13];
    const float* fc1_b = (const float*)d_in[14];
    const float* fc3_w = (const float*)d_in[15];
    const float* fc3_b = (const float*)d_in[16];
    const float* fc2_w = (const float*)d_in[17];
    const float* fc2_b = (const float*)d_in[18];
    float* out = (float*)d_out;

    float *buf0 = nullptr, *buf1 = nullptr;
    cudaGetSymbolAddress((void**)&buf0, g_buf0);
    cudaGetSymbolAddress((void**)&buf1, g_buf1);

    const int GRID = BATCH / B_TILE;   // 128

    lstm_mma<6,  false><<<GRID, NT, SM_TOTAL>>>(x,    w_ih0, w_hh0, b_ih0, b_hh0, buf0,
                                                nullptr, nullptr, nullptr, nullptr, nullptr, nullptr);
    lstm_mma<64, false><<<GRID, NT, SM_TOTAL>>>(buf0, w_ih1, w_hh1, b_ih1, b_hh1, buf1,
                                                nullptr, nullptr, nullptr, nullptr, nullptr, nullptr);
    lstm_mma<64, true ><<<GRID, NT, SM_TOTAL>>>(buf1, w_ih2, w_hh2, b_ih2, b_hh2, out,
                                                fc1_w, fc1_b, fc3_w, fc3_b, fc2_w, fc2_b);
}